// round 10
// baseline (speedup 1.0000x reference)
#include <cuda_runtime.h>
#include <cstdint>

// SphConv, tf32 mma.sync. D[n=(b,k) grouped, m=o]; A = weights (register-cached
// per K-eighth), B = x (ldmatrix from XOR-swizzled smem).
// CTA = 3 batches -> 135 lg-grouped rows; warps: 4 o32-ranges x 2 n-sets.
// Overlapping n8 blocks inside each lg-group; owner-predicated STG.

#define NCOEF 45
#define BSTRIDE (128 * NCOEF)
#define NROWS 135
#define SMEM_BYTES (NROWS * 128 * 4)    // 69120 -> 3 CTAs/SM

// A frags: g_wpA[((w16*5 + lg)*16 + ks)*32 + lane] =
//  {W[o][i], W[o+8][i], W[o][i+4], W[o+8][i+4]} * scale_lg/128 (tf32-rounded),
//  o = w16*16 + (lane>>2), i = ks*8 + (lane&3).
__device__ float4 g_wpA[8 * 5 * 16 * 32];

__global__ void prep_w(const float* __restrict__ w) {
    int idx  = blockIdx.x * blockDim.x + threadIdx.x;   // 20480 exactly
    int lane = idx & 31;
    int ks   = (idx >> 5) & 15;
    int t    = idx >> 9;
    int lg   = t % 5, w16 = t / 5;
    int o    = w16 * 16 + (lane >> 2);
    int i    = ks * 8 + (lane & 3);
    float l  = 2.0f * (float)lg;
    float s  = 6.28318530717958647692f *
               sqrtf(12.5663706143591729539f / (2.0f * l + 1.0f)) * (1.0f / 128.0f);
    float4 v;
    v.x = w[(o * 128 + i) * 5 + lg] * s;
    v.y = w[((o + 8) * 128 + i) * 5 + lg] * s;
    v.z = w[(o * 128 + i + 4) * 5 + lg] * s;
    v.w = w[((o + 8) * 128 + i + 4) * 5 + lg] * s;
    asm("cvt.rna.tf32.f32 %0, %0;" : "+f"(v.x));
    asm("cvt.rna.tf32.f32 %0, %0;" : "+f"(v.y));
    asm("cvt.rna.tf32.f32 %0, %0;" : "+f"(v.z));
    asm("cvt.rna.tf32.f32 %0, %0;" : "+f"(v.w));
    g_wpA[idx] = v;
}

__device__ __forceinline__ uint32_t smem_u32(const void* p) {
    uint32_t a;
    asm("{ .reg .u64 t; cvta.to.shared.u64 t, %1; cvt.u32.u64 %0, t; }" : "=r"(a) : "l"(p));
    return a;
}
__device__ __forceinline__ void ldsm4(uint32_t* r, uint32_t addr) {
    asm volatile("ldmatrix.sync.aligned.m8n8.x4.shared.b16 {%0,%1,%2,%3}, [%4];"
                 : "=r"(r[0]), "=r"(r[1]), "=r"(r[2]), "=r"(r[3]) : "r"(addr));
}
__device__ __forceinline__ void mma4(float* d, const float4& a,
                                     uint32_t b0, uint32_t b1) {
    asm volatile(
        "mma.sync.aligned.m16n8k8.row.col.f32.tf32.tf32.f32 "
        "{%0,%1,%2,%3}, {%4,%5,%6,%7}, {%8,%9}, {%0,%1,%2,%3};"
        : "+f"(d[0]), "+f"(d[1]), "+f"(d[2]), "+f"(d[3])
        : "r"(__float_as_uint(a.x)), "r"(__float_as_uint(a.y)),
          "r"(__float_as_uint(a.z)), "r"(__float_as_uint(a.w)),
          "r"(b0), "r"(b1));
}

// One lg-run: L overlapping n8 blocks, o32 (2 m16), K in 8 passes of 2 ks.
template <int LG, int L, int GBASE, int GEND, int WLO0,
          int B0, int B1, int B2, int B3, int B4>
__device__ __forceinline__ void do_run(uint32_t sbase, const float4* pA0,
                                       const float4* pA1, float* ob,
                                       int lane, int o0, int nvalid) {
    constexpr int BASES[5] = {B0, B1, B2, B3, B4};
    constexpr int NL  = 4 * LG + 1;
    constexpr int GLO = 2 * LG * LG - LG;
    const int lr = lane >> 2, lc = lane & 3;
    const int lrow = lane & 7, lt = lane >> 3;

    float acc[L][2][4];
    #pragma unroll
    for (int j = 0; j < L; j++)
        #pragma unroll
        for (int m = 0; m < 2; m++)
            #pragma unroll
            for (int e = 0; e < 4; e++) acc[j][m][e] = 0.0f;

    const float4* qA0 = pA0 + LG * 512;
    const float4* qA1 = pA1 + LG * 512;

    #pragma unroll
    for (int kp = 0; kp < 8; kp++) {
        const float4 a00 = qA0[(2 * kp) * 32];
        const float4 a01 = qA0[(2 * kp + 1) * 32];
        const float4 a10 = qA1[(2 * kp) * 32];
        const float4 a11 = qA1[(2 * kp + 1) * 32];
        #pragma unroll
        for (int j = 0; j < L; j++) {
            const int row = BASES[j] + lrow;
            const int g = kp * 4 + lt;
            uint32_t r[4];
            ldsm4(r, sbase + (uint32_t)(row * 512) +
                     (uint32_t)((g ^ (row & 7)) << 4));
            mma4(acc[j][0], a00, r[0], r[1]);
            mma4(acc[j][0], a01, r[2], r[3]);
            mma4(acc[j][1], a10, r[0], r[1]);
            mma4(acc[j][1], a11, r[2], r[3]);
        }
    }

    const int nvNL = nvalid * NL;
    #pragma unroll
    for (int j = 0; j < L; j++) {
        const int wlo = (j == 0) ? WLO0 : BASES[j - 1] + 8;
        const int whi = (BASES[j] + 8 < GEND) ? BASES[j] + 8 : GEND;
        #pragma unroll
        for (int e = 0; e < 4; e++) {
            const int n = BASES[j] + 2 * lc + (e & 1);
            const int local = n - GBASE;
            if (n >= wlo && n < whi && local < nvNL) {
                const int b_l = (local >= 2 * NL) ? 2 : (local >= NL) ? 1 : 0;
                const int k = GLO + local - b_l * NL;
                #pragma unroll
                for (int m = 0; m < 2; m++) {
                    const int o = o0 + m * 16 + lr + ((e >> 1) << 3);
                    ob[(size_t)b_l * BSTRIDE + o * NCOEF + k] = acc[j][m][e];
                }
            }
        }
    }
}

__global__ void __launch_bounds__(256, 3)
sph_r10(const float* __restrict__ x, float* __restrict__ out) {
    extern __shared__ __align__(16) float Xs[];   // [135][128], XOR-swizzled
    const int tid = threadIdx.x;
    const int nvalid = min(3, 16384 - (int)blockIdx.x * 3);
    const int limit = nvalid * BSTRIDE;

    // ---- fill: batched LDG (MLP 16) -> cvt.rna -> swizzled grouped STS ----
    {
        const float* src = x + (size_t)blockIdx.x * 3 * BSTRIDE + tid;
        int k = tid % 45, i = tid / 45, b_l = 0;
        #pragma unroll
        for (int batch = 0; batch < 5; batch++) {
            const int nb = (batch < 4) ? 16 : 4;
            float v[16];
            #pragma unroll
            for (int u = 0; u < 16; u++) {
                if (u < nb) {
                    const int e = (batch * 16 + u) * 256 + tid;
                    v[u] = (e < limit) ? __ldg(src + (size_t)(batch * 16 + u) * 256)
                                       : 0.0f;
                }
            }
            #pragma unroll
            for (int u = 0; u < 16; u++) {
                if (u < nb) {
                    const int e = (batch * 16 + u) * 256 + tid;
                    if (e < 3 * BSTRIDE) {
                        float val = v[u];
                        asm("cvt.rna.tf32.f32 %0, %0;" : "+f"(val));
                        const int lg = (k >= 28) ? 4 : (k >= 15) ? 3 : (k >= 6) ? 2
                                                  : (k >= 1) ? 1 : 0;
                        const int glo = 2 * lg * lg - lg;
                        const int glen = 4 * lg + 1;
                        const int row = 2 * glo + b_l * glen + k;
                        Xs[row * 128 + ((((i >> 2) ^ (row & 7)) << 2) | (i & 3))] = val;
                    }
                    k += 31; i += 5;
                    if (k >= 45) { k -= 45; i += 1; }
                    if (i >= 128) { i -= 128; b_l += 1; }
                }
            }
        }
    }
    __syncthreads();

    const int lane = tid & 31, wid = tid >> 5;
    const int ow = wid & 3, ns = wid >> 2;
    const uint32_t sbase = smem_u32(Xs);
    const float4* pA0 = g_wpA + (size_t)(ow * 2) * 2560 + lane;
    const float4* pA1 = g_wpA + (size_t)(ow * 2 + 1) * 2560 + lane;
    float* ob = out + (size_t)blockIdx.x * 3 * BSTRIDE;
    const int o0 = ow * 32;

    if (ns == 0) {
        do_run<0, 1, 0,  3,  0,  0,  0,  0,  0,  0>(sbase, pA0, pA1, ob, lane, o0, nvalid);
        do_run<1, 2, 3,  18, 3,  3,  10, 0,  0,  0>(sbase, pA0, pA1, ob, lane, o0, nvalid);
        do_run<2, 4, 18, 45, 18, 18, 26, 34, 37, 0>(sbase, pA0, pA1, ob, lane, o0, nvalid);
    } else {
        do_run<3, 5, 45, 84, 45, 45, 53, 61, 69, 76>(sbase, pA0, pA1, ob, lane, o0, nvalid);
        do_run<4, 4, 84, 135, 84, 84, 92, 100, 108, 0>(sbase, pA0, pA1, ob, lane, o0, nvalid);
        do_run<4, 3, 84, 135, 116, 116, 124, 127, 0, 0>(sbase, pA0, pA1, ob, lane, o0, nvalid);
    }
}

extern "C" void kernel_launch(void* const* d_in, const int* in_sizes, int n_in,
                              void* d_out, int out_size) {
    const float* x = (const float*)d_in[0];   // [16384, 128, 45] f32
    const float* w = (const float*)d_in[1];   // [128, 128, 5]   f32
    float* out = (float*)d_out;

    cudaFuncSetAttribute(sph_r10, cudaFuncAttributeMaxDynamicSharedMemorySize,
                         SMEM_BYTES);

    prep_w<<<80, 256>>>(w);
    sph_r10<<<5462, 256, SMEM_BYTES>>>(x, out);
}

// round 11
// speedup vs baseline: 1.4423x; 1.4423x over previous
#include <cuda_runtime.h>
#include <cstdint>

// SphConv, tf32 mma.sync, lg-grouped rows, overlapping m16 blocks (r8 core).
// New: transpose epilogue. Runs execute in DESCENDING lg order; each run dumps
// its acc into the same smem re-striped at 133 floats/row (disjoint from all
// still-live 132-stride rows), then one fully-coalesced linear STG pass.

#define NCOEF 45
#define BSTRIDE (128 * NCOEF)
#define XROW 132                        // MMA-phase row stride (528B, 16B-mult)
#define TROW 133                        // transpose-phase row stride (conflict-free)
#define SMEM_FLOATS 11970               // max(90*132, 90*133) -> 47880 B

__device__ float4 g_wpB[5 * 16 * 8 * 32];

__global__ void prep_w(const float* __restrict__ w) {
    int idx  = blockIdx.x * blockDim.x + threadIdx.x;   // 20480 exactly
    int lane = idx & 31;
    int ks2  = (idx >> 5) & 7;
    int nb   = (idx >> 8) & 15;
    int lg   = idx >> 12;
    int o    = nb * 8 + (lane >> 2);
    int i0   = ks2 * 16 + (lane & 3);
    float l  = 2.0f * (float)lg;
    float s  = 6.28318530717958647692f *
               sqrtf(12.5663706143591729539f / (2.0f * l + 1.0f)) * (1.0f / 128.0f);
    float4 v;
    v.x = w[(o * 128 + i0) * 5 + lg] * s;
    v.y = w[(o * 128 + i0 + 4) * 5 + lg] * s;
    v.z = w[(o * 128 + i0 + 8) * 5 + lg] * s;
    v.w = w[(o * 128 + i0 + 12) * 5 + lg] * s;
    asm("cvt.rna.tf32.f32 %0, %0;" : "+f"(v.x));
    asm("cvt.rna.tf32.f32 %0, %0;" : "+f"(v.y));
    asm("cvt.rna.tf32.f32 %0, %0;" : "+f"(v.z));
    asm("cvt.rna.tf32.f32 %0, %0;" : "+f"(v.w));
    g_wpB[idx] = v;
}

__device__ __forceinline__ uint32_t smem_u32(const void* p) {
    uint32_t a;
    asm("{ .reg .u64 t; cvta.to.shared.u64 t, %1; cvt.u32.u64 %0, t; }" : "=r"(a) : "l"(p));
    return a;
}
__device__ __forceinline__ void ldsm4(uint32_t* r, uint32_t addr) {
    asm volatile("ldmatrix.sync.aligned.m8n8.x4.shared.b16 {%0,%1,%2,%3}, [%4];"
                 : "=r"(r[0]), "=r"(r[1]), "=r"(r[2]), "=r"(r[3]) : "r"(addr));
}
__device__ __forceinline__ void mma4(float* d, const uint32_t* a,
                                     uint32_t b0, uint32_t b1) {
    asm volatile(
        "mma.sync.aligned.m16n8k8.row.col.f32.tf32.tf32.f32 "
        "{%0,%1,%2,%3}, {%4,%5,%6,%7}, {%8,%9}, {%0,%1,%2,%3};"
        : "+f"(d[0]), "+f"(d[1]), "+f"(d[2]), "+f"(d[3])
        : "r"(a[0]), "r"(a[1]), "r"(a[2]), "r"(a[3]), "r"(b0), "r"(b1));
}

// One lg-run (r8 MMA core). Ends with sync + acc dump into 133-stride smem.
template <int LG, int L, int B0, int B1, int B2>
__device__ __forceinline__ void do_run(float* Xs, uint32_t sA,
                                       const float4* wpBase,
                                       int lr, int lc, int o0) {
    constexpr int BASES[3] = {B0, B1, B2};
    constexpr int GLO  = 2 * LG * LG - LG;
    constexpr int GLEN = 4 * LG + 1;
    constexpr int GLO2 = 2 * GLO;
    constexpr int GHI2 = GLO2 + 2 * GLEN;

    const float4* p = wpBase + LG * 4096;

    float acc[L][8];
    #pragma unroll
    for (int j = 0; j < L; j++)
        #pragma unroll
        for (int q = 0; q < 8; q++) acc[j][q] = 0.0f;

    #pragma unroll
    for (int h = 0; h < 2; h++) {
        float4 b4[2][4];
        #pragma unroll
        for (int nb2 = 0; nb2 < 2; nb2++)
            #pragma unroll
            for (int q = 0; q < 4; q++)
                b4[nb2][q] = p[nb2 * 256 + (h * 4 + q) * 32];

        #pragma unroll
        for (int j = 0; j < L; j++) {
            const uint32_t ab = sA + (uint32_t)(BASES[j] * (XROW * 4) + h * 256);
            uint32_t a0[4], a1[4];
            ldsm4(a0, ab);
            #pragma unroll
            for (int ks = 0; ks < 8; ks++) {
                uint32_t* ac = (ks & 1) ? a1 : a0;
                uint32_t* an = (ks & 1) ? a0 : a1;
                if (ks < 7) ldsm4(an, ab + (uint32_t)((ks + 1) * 32));
                const int q = ks >> 1;
                uint32_t w00, w01, w10, w11;
                if (ks & 1) {
                    w00 = __float_as_uint(b4[0][q].z); w01 = __float_as_uint(b4[0][q].w);
                    w10 = __float_as_uint(b4[1][q].z); w11 = __float_as_uint(b4[1][q].w);
                } else {
                    w00 = __float_as_uint(b4[0][q].x); w01 = __float_as_uint(b4[0][q].y);
                    w10 = __float_as_uint(b4[1][q].x); w11 = __float_as_uint(b4[1][q].y);
                }
                mma4(&acc[j][0], ac, w00, w01);
                mma4(&acc[j][4], ac, w10, w11);
            }
        }
    }

    // all warps done reading this run's 132-rows before re-striping them
    __syncthreads();

    #pragma unroll
    for (int j = 0; j < L; j++) {
        #pragma unroll
        for (int hh = 0; hh < 2; hh++) {
            const int g = BASES[j] + lr + hh * 8;
            if (g >= GLO2 && g < GHI2) {
                float* t = Xs + g * TROW + o0 + 2 * lc;
                t[0] = acc[j][hh * 2];
                t[1] = acc[j][hh * 2 + 1];
                t[8] = acc[j][4 + hh * 2];
                t[9] = acc[j][4 + hh * 2 + 1];
            }
        }
    }
}

__global__ void __launch_bounds__(256, 3)
sph_r11(const float* __restrict__ x, float* __restrict__ out) {
    __shared__ __align__(16) float Xs[SMEM_FLOATS];
    const int tid = threadIdx.x;

    // ---- fill (r8): batched LDG (MLP 16) -> cvt.rna -> grouped STS ----
    {
        const float* src = x + (size_t)blockIdx.x * 2 * BSTRIDE + tid;
        int k = tid % 45, i = tid / 45, b_l = 0;
        int t = 0;
        #pragma unroll
        for (int batch = 0; batch < 3; batch++) {
            const int nb = (batch < 2) ? 16 : 13;
            float v[16];
            #pragma unroll
            for (int u = 0; u < 16; u++)
                if (u < nb) v[u] = __ldg(src + (size_t)(t + u) * 256);
            #pragma unroll
            for (int u = 0; u < 16; u++) {
                if (u < nb) {
                    float val = v[u];
                    asm("cvt.rna.tf32.f32 %0, %0;" : "+f"(val));
                    const int lg = (k >= 28) ? 4 : (k >= 15) ? 3 : (k >= 6) ? 2
                                              : (k >= 1) ? 1 : 0;
                    const int glo = 2 * lg * lg - lg;
                    const int glen = 4 * lg + 1;
                    const int row = 2 * glo + b_l * glen + (k - glo);
                    Xs[row * XROW + i] = val;
                    k += 31; i += 5;
                    if (k >= 45) { k -= 45; i += 1; }
                    if (i >= 128) { i -= 128; b_l = 1; }
                }
            }
            t += nb;
        }
    }
    __syncthreads();

    const int lane = tid & 31, wid = tid >> 5;
    const int lr = lane >> 2, lc = lane & 3;
    const uint32_t sbase = smem_u32(Xs);
    const uint32_t sA = sbase + (uint32_t)(((lane & 15) * XROW) * 4
                                           + ((lane >> 4) * 16));
    const float4* wpBase = g_wpB + wid * 512 + lane;
    const int o0 = wid * 16;

    // descending lg: each run's 133-stride writes stay below all
    // still-live 132-stride rows of later (lower-lg) runs.
    do_run<4, 3, 56, 72, 74>(Xs, sA, wpBase, lr, lc, o0);
    do_run<3, 2, 30, 40, 0 >(Xs, sA, wpBase, lr, lc, o0);
    do_run<2, 2, 12, 14, 0 >(Xs, sA, wpBase, lr, lc, o0);
    do_run<1, 1, 2,  0,  0 >(Xs, sA, wpBase, lr, lc, o0);
    do_run<0, 1, 0,  0,  0 >(Xs, sA, wpBase, lr, lc, o0);
    __syncthreads();

    // ---- coalesced linear STG pass: warp owns 1440 consecutive floats ----
    {
        const int b = wid >> 2;
        float* ob = out + (size_t)blockIdx.x * 2 * BSTRIDE
                    + (size_t)b * BSTRIDE + (wid & 3) * 1440;
        int k0 = 0;
        int o_it = (wid & 3) * 32;
        #pragma unroll 5
        for (int it = 0; it < 45; it++) {
            int kk = k0 + lane;
            int oo = o_it;
            if (kk >= 45) { kk -= 45; oo += 1; }
            const int lg = (kk >= 28) ? 4 : (kk >= 15) ? 3 : (kk >= 6) ? 2
                                        : (kk >= 1) ? 1 : 0;
            const int glo  = 2 * lg * lg - lg;
            const int glen = 4 * lg + 1;
            const int row  = kk + glo + b * glen;
            ob[it * 32 + lane] = Xs[row * TROW + oo];
            k0 += 32;
            if (k0 >= 45) { k0 -= 45; o_it += 1; }
        }
    }
}

extern "C" void kernel_launch(void* const* d_in, const int* in_sizes, int n_in,
                              void* d_out, int out_size) {
    const float* x = (const float*)d_in[0];   // [16384, 128, 45] f32
    const float* w = (const float*)d_in[1];   // [128, 128, 5]   f32
    float* out = (float*)d_out;

    prep_w<<<80, 256>>>(w);
    sph_r11<<<8192, 256>>>(x, out);
}

// round 12
// speedup vs baseline: 1.5337x; 1.0634x over previous
#include <cuda_runtime.h>
#include <cstdint>

// SphConv, tf32 mma.sync. r8 core with o32 warps (4 warps/CTA, each owns 32
// o-cols, iterates all 9 m-blocks) + row-table decode + r11 transpose epilogue.
// CTA = 2 batches, 90 lg-grouped rows. Weights = B operand, K-quarter staged.

#define NCOEF 45
#define BSTRIDE (128 * NCOEF)
#define XROW 132                        // MMA-phase row stride (528B)
#define TROW 133                        // transpose-phase row stride
#define SMEM_FLOATS 11970               // 90*133 = 47880 B

__device__ float4 g_wpB[5 * 16 * 8 * 32];

__global__ void prep_w(const float* __restrict__ w) {
    int idx  = blockIdx.x * blockDim.x + threadIdx.x;   // 20480 exactly
    int lane = idx & 31;
    int ks2  = (idx >> 5) & 7;
    int nb   = (idx >> 8) & 15;
    int lg   = idx >> 12;
    int o    = nb * 8 + (lane >> 2);
    int i0   = ks2 * 16 + (lane & 3);
    float l  = 2.0f * (float)lg;
    float s  = 6.28318530717958647692f *
               sqrtf(12.5663706143591729539f / (2.0f * l + 1.0f)) * (1.0f / 128.0f);
    float4 v;
    v.x = w[(o * 128 + i0) * 5 + lg] * s;
    v.y = w[(o * 128 + i0 + 4) * 5 + lg] * s;
    v.z = w[(o * 128 + i0 + 8) * 5 + lg] * s;
    v.w = w[(o * 128 + i0 + 12) * 5 + lg] * s;
    asm("cvt.rna.tf32.f32 %0, %0;" : "+f"(v.x));
    asm("cvt.rna.tf32.f32 %0, %0;" : "+f"(v.y));
    asm("cvt.rna.tf32.f32 %0, %0;" : "+f"(v.z));
    asm("cvt.rna.tf32.f32 %0, %0;" : "+f"(v.w));
    g_wpB[idx] = v;
}

__device__ __forceinline__ uint32_t smem_u32(const void* p) {
    uint32_t a;
    asm("{ .reg .u64 t; cvta.to.shared.u64 t, %1; cvt.u32.u64 %0, t; }" : "=r"(a) : "l"(p));
    return a;
}
__device__ __forceinline__ void ldsm4(uint32_t* r, uint32_t addr) {
    asm volatile("ldmatrix.sync.aligned.m8n8.x4.shared.b16 {%0,%1,%2,%3}, [%4];"
                 : "=r"(r[0]), "=r"(r[1]), "=r"(r[2]), "=r"(r[3]) : "r"(addr));
}
__device__ __forceinline__ void mma4(float* d, const uint32_t* a,
                                     uint32_t b0, uint32_t b1) {
    asm volatile(
        "mma.sync.aligned.m16n8k8.row.col.f32.tf32.tf32.f32 "
        "{%0,%1,%2,%3}, {%4,%5,%6,%7}, {%8,%9}, {%0,%1,%2,%3};"
        : "+f"(d[0]), "+f"(d[1]), "+f"(d[2]), "+f"(d[3])
        : "r"(a[0]), "r"(a[1]), "r"(a[2]), "r"(a[3]), "r"(b0), "r"(b1));
}

// One lg-run: L overlapping m16 blocks, warp covers o32 (4 n8 sets).
// K staged in quarters (32 weight regs). Ends: sync + 133-stride acc dump.
template <int LG, int L, int B0, int B1, int B2>
__device__ __forceinline__ void do_run(float* Xs, uint32_t sA,
                                       const float4* pw4,  // + wid*4 nb offset
                                       int wid, int lr, int lc) {
    constexpr int BASES[3] = {B0, B1, B2};
    constexpr int GLO  = 2 * LG * LG - LG;
    constexpr int GLEN = 4 * LG + 1;
    constexpr int GLO2 = 2 * GLO;
    constexpr int GHI2 = GLO2 + 2 * GLEN;

    const float4* pw = pw4 + LG * 4096;

    float acc[L][4][4];
    #pragma unroll
    for (int j = 0; j < L; j++)
        #pragma unroll
        for (int nb4 = 0; nb4 < 4; nb4++)
            #pragma unroll
            for (int e = 0; e < 4; e++) acc[j][nb4][e] = 0.0f;

    #pragma unroll
    for (int q = 0; q < 4; q++) {
        float4 w4[4][2];
        #pragma unroll
        for (int nb4 = 0; nb4 < 4; nb4++)
            #pragma unroll
            for (int s = 0; s < 2; s++)
                w4[nb4][s] = pw[nb4 * 256 + (2 * q + s) * 32];

        #pragma unroll
        for (int t4 = 0; t4 < 4; t4++) {
            uint32_t ar[L][4];
            #pragma unroll
            for (int j = 0; j < L; j++)
                ldsm4(ar[j], sA + (uint32_t)(BASES[j] * (XROW * 4))
                             + (uint32_t)((4 * q + t4) * 32));
            #pragma unroll
            for (int j = 0; j < L; j++) {
                #pragma unroll
                for (int nb4 = 0; nb4 < 4; nb4++) {
                    uint32_t b0, b1;
                    if (t4 & 1) {
                        b0 = __float_as_uint(w4[nb4][t4 >> 1].z);
                        b1 = __float_as_uint(w4[nb4][t4 >> 1].w);
                    } else {
                        b0 = __float_as_uint(w4[nb4][t4 >> 1].x);
                        b1 = __float_as_uint(w4[nb4][t4 >> 1].y);
                    }
                    mma4(acc[j][nb4], ar[j], b0, b1);
                }
            }
        }
    }

    __syncthreads();   // all warps done ldsm-reading this run's 132-rows

    #pragma unroll
    for (int j = 0; j < L; j++) {
        #pragma unroll
        for (int hh = 0; hh < 2; hh++) {
            const int g = BASES[j] + lr + hh * 8;
            if (g >= GLO2 && g < GHI2) {
                float* t = Xs + g * TROW + wid * 32 + 2 * lc;
                #pragma unroll
                for (int nb4 = 0; nb4 < 4; nb4++) {
                    t[nb4 * 8]     = acc[j][nb4][hh * 2];
                    t[nb4 * 8 + 1] = acc[j][nb4][hh * 2 + 1];
                }
            }
        }
    }
}

__global__ void __launch_bounds__(128, 4)
sph_r12(const float* __restrict__ x, float* __restrict__ out) {
    __shared__ __align__(16) float Xs[SMEM_FLOATS];
    __shared__ int rowTab[90];
    const int tid = threadIdx.x;
    const int lane = tid & 31, wid = tid >> 5;

    // ---- row table: (b*45 + k) -> grouped row ----
    if (tid < 90) {
        const int b = tid / 45, k = tid - b * 45;
        const int lg = (k >= 28) ? 4 : (k >= 15) ? 3 : (k >= 6) ? 2
                                   : (k >= 1) ? 1 : 0;
        rowTab[tid] = k + (2 * lg * lg - lg) + b * (4 * lg + 1);
    }
    __syncthreads();

    // ---- fill: batched LDG (MLP 15) -> cvt.rna -> table-decoded STS ----
    {
        const float* src = x + (size_t)blockIdx.x * 2 * BSTRIDE + tid;
        int k = tid % 45, i = tid / 45, b_l = 0;
        #pragma unroll
        for (int batch = 0; batch < 6; batch++) {
            float v[15];
            #pragma unroll
            for (int u = 0; u < 15; u++)
                v[u] = __ldg(src + (size_t)(batch * 15 + u) * 128);
            #pragma unroll
            for (int u = 0; u < 15; u++) {
                float val = v[u];
                asm("cvt.rna.tf32.f32 %0, %0;" : "+f"(val));
                Xs[rowTab[b_l * 45 + k] * XROW + i] = val;
                k += 38; i += 2;                   // advance by 128
                if (k >= 45) { k -= 45; i += 1; }
                if (i >= 128) { i -= 128; b_l = 1; }
            }
        }
    }
    __syncthreads();

    const int lr = lane >> 2, lc = lane & 3;
    const uint32_t sbase = smem_u32(Xs);
    const uint32_t sA = sbase + (uint32_t)(((lane & 15) * XROW) * 4
                                           + ((lane >> 4) << 4));
    const float4* pw4 = g_wpB + (size_t)(wid * 4) * 256 + lane;

    // descending lg (region-disjoint transpose writes)
    do_run<4, 3, 56, 72, 74>(Xs, sA, pw4, wid, lr, lc);
    do_run<3, 2, 30, 40, 0 >(Xs, sA, pw4, wid, lr, lc);
    do_run<2, 2, 12, 14, 0 >(Xs, sA, pw4, wid, lr, lc);
    do_run<1, 1, 2,  0,  0 >(Xs, sA, pw4, wid, lr, lc);
    do_run<0, 1, 0,  0,  0 >(Xs, sA, pw4, wid, lr, lc);
    __syncthreads();

    // ---- coalesced linear STG: warp owns batch (wid>>1), o-half (wid&1) ----
    {
        const int b = wid >> 1;
        const int o_base = (wid & 1) * 64;
        float* ob = out + (size_t)blockIdx.x * 2 * BSTRIDE
                    + (size_t)b * BSTRIDE + o_base * NCOEF;
        const int* tabB = rowTab + b * 45;
        int k = lane, o = 0;
        #pragma unroll 5
        for (int it = 0; it < 90; it++) {
            ob[it * 32 + lane] = Xs[tabB[k] * TROW + o_base + o];
            k += 32;
            if (k >= 45) { k -= 45; o += 1; }
        }
    }
}

extern "C" void kernel_launch(void* const* d_in, const int* in_sizes, int n_in,
                              void* d_out, int out_size) {
    const float* x = (const float*)d_in[0];   // [16384, 128, 45] f32
    const float* w = (const float*)d_in[1];   // [128, 128, 5]   f32
    float* out = (float*)d_out;

    prep_w<<<80, 256>>>(w);
    sph_r12<<<8192, 128>>>(x, out);
}